// round 14
// baseline (speedup 1.0000x reference)
#include <cuda_runtime.h>
#include <cstdint>
#include <math_constants.h>

#define NN   1024
#define BB   128
#define SPLITK 16
#define KS   (NN / SPLITK)   // 64 k per block
#define BK   32              // k chunk in smem
#define BM   128             // b tile = full batch
#define BN   128             // j tile
#define NT   1024            // 32 warps, 1 block/SM
#define XS_STRIDE 132        // 128 + 4 pad, 16B-aligned rows

#define XS_FLOATS (BK * XS_STRIDE)                 // 32*132 = 4224
#define WS_FLOATS (2 * BK * BN)                    // 8192
#define SMEM_BYTES ((XS_FLOATS + WS_FLOATS) * 4)   // 16896 + 32768 = 49664

// split-K partials: [SPLITK][BB][NN] = 8 MB
__device__ float g_partials[SPLITK * BB * NN];
// opaque -1.0f so ptxas cannot fold the FFMA back into FADD
__device__ float g_negone = -1.0f;

__device__ __forceinline__ void cp_async16(uint32_t dst_smem, const void* src) {
    asm volatile("cp.async.cg.shared.global [%0], [%1], 16;\n"
                 :: "r"(dst_smem), "l"(src));
}
__device__ __forceinline__ void cp_commit() {
    asm volatile("cp.async.commit_group;\n" ::: "memory");
}
__device__ __forceinline__ void cp_wait0() {
    asm volatile("cp.async.wait_group 0;\n" ::: "memory");
}

__global__ void __launch_bounds__(NT, 1)
tropical_main(const float* __restrict__ x,
              const float* __restrict__ w)
{
    extern __shared__ float smem[];
    float* xs = smem;                 // [BK][XS_STRIDE] transposed x: [k][b], all 128 b
    float* ws = smem + XS_FLOATS;     // [2][BK][BN]     natural w:    [k][j]

    const int tid = threadIdx.x;
    const int tx  = tid & 31;        // j group (0..31) -> 4 j each
    const int ty  = tid >> 5;        // b group = warp id (0..31) -> 4 b each
    const int j0  = blockIdx.x * BN;
    const int k0  = blockIdx.z * KS;

    // x staging: 1 float4 per thread per chunk (128 b-rows x 32 k = 4096 f4... /4)
    const int xb  = tid >> 3;              // 0..127
    const int xk4 = (tid & 7) << 2;        // 0..28 step 4
    // ws staging: 1 cp16 per thread per chunk (32 rows x 128 j)
    const int wrow = tid >> 5;             // 0..31
    const int wc4  = (tid & 31) << 2;      // 0..124 step 4

    const float negone = g_negone;         // runtime -> genuine FFMA

    float acc[4][4];
    #pragma unroll
    for (int r = 0; r < 4; r++)
        #pragma unroll
        for (int c = 0; c < 4; c++)
            acc[r][c] = -CUDART_INF_F;

    // ---- prologue: chunk 0 -> xs + ws[0] ----
    {
        float4 xr = *reinterpret_cast<const float4*>(&x[xb * NN + k0 + xk4]);
        xs[(xk4 + 0) * XS_STRIDE + xb] = xr.x;
        xs[(xk4 + 1) * XS_STRIDE + xb] = xr.y;
        xs[(xk4 + 2) * XS_STRIDE + xb] = xr.z;
        xs[(xk4 + 3) * XS_STRIDE + xb] = xr.w;
        uint32_t d = (uint32_t)__cvta_generic_to_shared(&ws[wrow * BN + wc4]);
        cp_async16(d, &w[(k0 + wrow) * NN + j0 + wc4]);
        cp_commit();
        cp_wait0();
        __syncthreads();
    }

    // ---- prefetch chunk 1: x into regs, ws via cp.async ----
    float4 xn;
    {
        const int kb = k0 + BK;
        xn = *reinterpret_cast<const float4*>(&x[xb * NN + kb + xk4]);
        uint32_t d = (uint32_t)__cvta_generic_to_shared(&ws[BK * BN + wrow * BN + wc4]);
        cp_async16(d, &w[(kb + wrow) * NN + j0 + wc4]);
        cp_commit();
    }

    const int jq = tx << 2;   // 0..124 step 4
    const int bq = ty << 2;   // 0..124 step 4

    // ---- compute chunk 0 ----
    #pragma unroll
    for (int k = 0; k < BK; k++) {
        float4 xv = *reinterpret_cast<const float4*>(&xs[k * XS_STRIDE + bq]);  // warp bcast
        float4 wv = *reinterpret_cast<const float4*>(&ws[k * BN + jq]);
        float xr4[4] = {xv.x, xv.y, xv.z, xv.w};
        float wl[4]  = {wv.x, wv.y, wv.z, wv.w};
        #pragma unroll
        for (int r = 0; r < 4; r++)
            #pragma unroll
            for (int c = 0; c < 4; c++)
                acc[r][c] = fmaxf(acc[r][c], __fmaf_rn(wl[c], negone, xr4[r]));
    }

    // ---- drain readers, stage x chunk 1 ----
    __syncthreads();
    xs[(xk4 + 0) * XS_STRIDE + xb] = xn.x;
    xs[(xk4 + 1) * XS_STRIDE + xb] = xn.y;
    xs[(xk4 + 2) * XS_STRIDE + xb] = xn.z;
    xs[(xk4 + 3) * XS_STRIDE + xb] = xn.w;
    cp_wait0();
    __syncthreads();

    // ---- compute chunk 1 ----
    #pragma unroll
    for (int k = 0; k < BK; k++) {
        float4 xv = *reinterpret_cast<const float4*>(&xs[k * XS_STRIDE + bq]);
        float4 wv = *reinterpret_cast<const float4*>(&ws[BK * BN + k * BN + jq]);
        float xr4[4] = {xv.x, xv.y, xv.z, xv.w};
        float wl[4]  = {wv.x, wv.y, wv.z, wv.w};
        #pragma unroll
        for (int r = 0; r < 4; r++)
            #pragma unroll
            for (int c = 0; c < 4; c++)
                acc[r][c] = fmaxf(acc[r][c], __fmaf_rn(wl[c], negone, xr4[r]));
    }

    // ---- write partials (plain STG.128) ----
    float* p = &g_partials[blockIdx.z * (BB * NN)];
    #pragma unroll
    for (int r = 0; r < 4; r++) {
        float4 o;
        o.x = acc[r][0]; o.y = acc[r][1]; o.z = acc[r][2]; o.w = acc[r][3];
        *reinterpret_cast<float4*>(&p[(bq + r) * NN + j0 + jq]) = o;
    }
}

__global__ void __launch_bounds__(256, 8)
tropical_reduce(const float* __restrict__ bias,
                float* __restrict__ out)
{
    const int i = blockIdx.x * 256 + threadIdx.x;
    float m = g_partials[i];
    #pragma unroll
    for (int s = 1; s < SPLITK; s++)
        m = fmaxf(m, g_partials[s * (BB * NN) + i]);
    out[i] = m + bias[i & (NN - 1)];
}

extern "C" void kernel_launch(void* const* d_in, const int* in_sizes, int n_in,
                              void* d_out, int out_size) {
    const float* x    = (const float*)d_in[0];   // [128, 1024]
    const float* wgt  = (const float*)d_in[1];   // [1024, 1024]
    const float* bias = (const float*)d_in[2];   // [1024]
    float* out = (float*)d_out;                  // [128, 1024]

    cudaFuncSetAttribute(tropical_main,
                         cudaFuncAttributeMaxDynamicSharedMemorySize, SMEM_BYTES);

    dim3 grid(NN / BN, 1, SPLITK);               // (8, 1, 16) = 128 blocks, 1/SM
    tropical_main<<<grid, NT, SMEM_BYTES>>>(x, wgt);

    const int total = BB * NN;                   // 131072
    tropical_reduce<<<total / 256, 256>>>(bias, out);   // 512 blocks
}